// round 5
// baseline (speedup 1.0000x reference)
#include <cuda_runtime.h>
#include <math_constants.h>

// Problem constants
#define K_CODES 1024
#define C_DIM   256
#define N_PIX   32768
#define ZQ_ELEMS 8388608       // 32*256*32*32

// Tiling
#define TM 64                  // pixels per block
#define TN 128                 // codes per k-chunk
#define CC 16                  // channels per stage
#define NTHREADS 128           // 16 tx (codes) x 8 ty (pixel rows)
#define NKC 8                  // k-chunks
#define NCC 16                 // c-chunks
#define NSTAGES (NKC * NCC)    // 128
#define RING 3

#define ZS_F   (CC * TM)       // 1024 floats  (4KB)
#define WS_F   (CC * TN * 2)   // 4096 floats  (16KB, duplicated codebook)
#define STAGE_F (ZS_F + WS_F)  // 5120 floats  (20KB)
#define SMEM_BYTES (RING * STAGE_F * 4)   // 61440

// Normalized codebook: row-major (gather) and stage-packed DUPLICATED (GEMM)
__device__ float g_wn[K_CODES * C_DIM];           // [k][c]
__device__ float g_wp[NSTAGES * WS_F];            // 2MB, each value stored twice

// ---------------------------------------------------------------------------
__device__ __forceinline__ void ffma2(unsigned long long& d,
                                      unsigned long long a,
                                      unsigned long long b) {
    asm("fma.rn.f32x2 %0, %1, %2, %0;" : "+l"(d) : "l"(a), "l"(b));
}
__device__ __forceinline__ void unpack2(unsigned long long v, float& lo, float& hi) {
    asm("mov.b64 {%0, %1}, %2;" : "=f"(lo), "=f"(hi) : "l"(v));
}
__device__ __forceinline__ unsigned int smem_u32(const void* p) {
    return (unsigned int)__cvta_generic_to_shared(p);
}
__device__ __forceinline__ void cp16(unsigned int dst, const void* src) {
    asm volatile("cp.async.cg.shared.global [%0], [%1], 16;" :: "r"(dst), "l"(src));
}
__device__ __forceinline__ void cp_commit() {
    asm volatile("cp.async.commit_group;");
}
template<int N>
__device__ __forceinline__ void cp_wait() {
    asm volatile("cp.async.wait_group %0;" :: "n"(N));
}

// ---------------------------------------------------------------------------
// Kernel 1: L2-normalize codebook rows -> g_wn (row-major) + g_wp (stage-
// packed, duplicated pairs, lane-interleaved for conflict-free LDS.128).
// Layout of g_wp stage s = kcI*16 + ccI, for code k (kk=k&127) channel c:
//   bq = kk>>5, lane = (kk&31)>>1, j = kk&1
//   pos = (c&15)*256 + bq*64 + lane*4 + j*2   (value stored at pos and pos+1)
// ---------------------------------------------------------------------------
__global__ void vq_norm_weight_kernel(const float* __restrict__ w) {
    const int k = blockIdx.x;
    const int t = threadIdx.x;           // channel
    float v = w[k * C_DIM + t];
    float s = v * v;
    #pragma unroll
    for (int off = 16; off; off >>= 1)
        s += __shfl_xor_sync(0xffffffffu, s, off);
    __shared__ float ssum[8];
    if ((t & 31) == 0) ssum[t >> 5] = s;
    __syncthreads();
    float tot = ssum[0] + ssum[1] + ssum[2] + ssum[3]
              + ssum[4] + ssum[5] + ssum[6] + ssum[7];
    float den = fmaxf(sqrtf(tot), 1e-12f);
    float o = v / den;
    g_wn[k * C_DIM + t] = o;

    int kcI = k >> 7, ccI = t >> 4, cl = t & 15;
    int kk = k & 127;
    int bq = kk >> 5, lane = (kk & 31) >> 1, j = kk & 1;
    size_t pos = (size_t)(kcI * NCC + ccI) * WS_F
               + cl * 256 + bq * 64 + lane * 4 + j * 2;
    g_wp[pos]     = o;
    g_wp[pos + 1] = o;
}

// ---------------------------------------------------------------------------
// Kernel 2: argmax_k <z_n, w_k> + gather z_q. 512 blocks x 128 threads.
// 60KB dynamic smem ring (3 stages) -> 3 blocks/SM.
// ---------------------------------------------------------------------------
__global__ __launch_bounds__(NTHREADS, 3)
void vq_argmax_kernel(const float* __restrict__ z,
                      float* __restrict__ out,
                      int write_idx) {
    extern __shared__ float sm[];        // RING * STAGE_F floats

    const int tid = threadIdx.x;
    const int tx = tid & 15;             // code lane
    const int ty = tid >> 4;             // pixel row -> pixels ty*8..ty*8+7
    const int n0 = blockIdx.x * TM;
    const int b   = n0 >> 10;
    const int hw0 = n0 & 1023;
    const float* zbase = z + (((size_t)b * C_DIM) << 10) + hw0;

    // ---- stage fill: all linear 16B cp.async ----
    auto fill = [&](int s) {
        float* buf = sm + (s % RING) * STAGE_F;
        const int ccI = s & (NCC - 1);
        #pragma unroll
        for (int t = 0; t < 2; t++) {            // zs: 256 float4
            int i  = tid + t * NTHREADS;
            int c  = i >> 4;
            int p4 = i & 15;
            cp16(smem_u32(buf + i * 4),
                 zbase + (((size_t)(ccI * CC + c)) << 10) + p4 * 4);
        }
        const float* wsrc = g_wp + (size_t)s * WS_F;
        #pragma unroll
        for (int t = 0; t < 8; t++) {            // wdup: 1024 float4
            int i = tid + t * NTHREADS;
            cp16(smem_u32(buf + ZS_F + i * 4), wsrc + i * 4);
        }
        cp_commit();
    };

    fill(0);
    fill(1);

    float rbv[8];
    int   rbi[8];
    #pragma unroll
    for (int i = 0; i < 8; i++) { rbv[i] = -CUDART_INF_F; rbi[i] = 0; }

    int s = 0;
    for (int kcI = 0; kcI < NKC; kcI++) {
        unsigned long long acc[4][8];    // [pixel-pair][code kk=bq*2+j]
        #pragma unroll
        for (int i = 0; i < 4; i++)
            #pragma unroll
            for (int j = 0; j < 8; j++) acc[i][j] = 0ull;

        for (int ccI = 0; ccI < NCC; ccI++, s++) {
            if (s + 1 < NSTAGES) cp_wait<1>(); else cp_wait<0>();
            __syncthreads();
            if (s + 2 < NSTAGES) fill(s + 2);

            const float* zb = sm + (s % RING) * STAGE_F;
            const float* wb = zb + ZS_F;

            #pragma unroll 4
            for (int c = 0; c < CC; c++) {
                const float* zr = zb + c * TM + (ty << 3);
                ulonglong2 z01 = *(const ulonglong2*)zr;        // px pairs 0,1
                ulonglong2 z23 = *(const ulonglong2*)(zr + 4);  // px pairs 2,3
                unsigned long long zp[4] = { z01.x, z01.y, z23.x, z23.y };
                const float* wr = wb + c * (TN * 2) + (tx << 2);
                #pragma unroll
                for (int bq = 0; bq < 4; bq++) {
                    ulonglong2 w = *(const ulonglong2*)(wr + bq * 64);
                    #pragma unroll
                    for (int p2 = 0; p2 < 4; p2++) {
                        ffma2(acc[p2][bq * 2 + 0], zp[p2], w.x);
                        ffma2(acc[p2][bq * 2 + 1], zp[p2], w.y);
                    }
                }
            }
        }

        // ---- chunk argmax. Thread's codes: k = kc + bq*32 + 2*tx + j ----
        const int kc = kcI * TN;
        #pragma unroll
        for (int p2 = 0; p2 < 4; p2++) {
            float bvL = -CUDART_INF_F, bvH = -CUDART_INF_F;
            int   bkL = 0, bkH = 0;
            #pragma unroll
            for (int bq = 0; bq < 4; bq++) {
                #pragma unroll
                for (int j = 0; j < 2; j++) {
                    float lo, hi;
                    unpack2(acc[p2][bq * 2 + j], lo, hi);
                    int k0 = kc + bq * 32 + (tx << 1) + j;
                    if (lo > bvL) { bvL = lo; bkL = k0; }  // increasing k: first wins
                    if (hi > bvH) { bvH = hi; bkH = k0; }
                }
            }
            #pragma unroll
            for (int off = 8; off; off >>= 1) {     // reduce across 16 tx lanes
                float ov = __shfl_xor_sync(0xffffffffu, bvL, off);
                int   ok = __shfl_xor_sync(0xffffffffu, bkL, off);
                if (ov > bvL || (ov == bvL && ok < bkL)) { bvL = ov; bkL = ok; }
                ov = __shfl_xor_sync(0xffffffffu, bvH, off);
                ok = __shfl_xor_sync(0xffffffffu, bkH, off);
                if (ov > bvH || (ov == bvH && ok < bkH)) { bvH = ov; bkH = ok; }
            }
            int i0 = p2 * 2;
            if (bvL > rbv[i0])     { rbv[i0]     = bvL; rbi[i0]     = bkL; }
            if (bvH > rbv[i0 + 1]) { rbv[i0 + 1] = bvH; rbi[i0 + 1] = bkH; }
        }
    }

    // ---- publish per-pixel indices ----
    __syncthreads();                 // all compute done; smem reusable
    int* sbidx = (int*)sm;
    if (tx == 0) {
        #pragma unroll
        for (int i = 0; i < 8; i++) sbidx[(ty << 3) + i] = rbi[i];
    }
    __syncthreads();

    // ---- write z_q: out[b][c][hw0+p] = g_wn[idx[p]][c], coalesced over p ----
    #pragma unroll 4
    for (int i = tid; i < C_DIM * TM; i += NTHREADS) {
        int p = i & (TM - 1);
        int c = i >> 6;
        out[(((size_t)(b * C_DIM + c)) << 10) + hw0 + p] =
            g_wn[(size_t)sbidx[p] * C_DIM + c];
    }
    if (write_idx && tid < TM) {
        out[ZQ_ELEMS + n0 + tid] = (float)sbidx[tid];
    }
}

// ---------------------------------------------------------------------------
extern "C" void kernel_launch(void* const* d_in, const int* in_sizes, int n_in,
                              void* d_out, int out_size) {
    const float* z_e    = (const float*)d_in[0];
    const float* weight = (const float*)d_in[1];
    float* out = (float*)d_out;

    const int write_idx = (out_size >= ZQ_ELEMS + N_PIX) ? 1 : 0;

    static int smem_set = 0;
    if (!smem_set) {
        cudaFuncSetAttribute(vq_argmax_kernel,
                             cudaFuncAttributeMaxDynamicSharedMemorySize,
                             SMEM_BYTES);
        smem_set = 1;
    }

    vq_norm_weight_kernel<<<K_CODES, C_DIM>>>(weight);
    vq_argmax_kernel<<<N_PIX / TM, NTHREADS, SMEM_BYTES>>>(z_e, out, write_idx);
}

// round 6
// speedup vs baseline: 1.3194x; 1.3194x over previous
#include <cuda_runtime.h>
#include <math_constants.h>

// Problem constants
#define K_CODES 1024
#define C_DIM   256
#define N_PIX   32768
#define ZQ_ELEMS 8388608       // 32*256*32*32

// Tiling
#define TM 32                  // pixels per block
#define TN 128                 // codes per k-chunk
#define CC 32                  // channels per stage
#define NTHREADS 128           // 16 tx (codes) x 8 ty (pixel rows), 4 px per row
#define NKC 8                  // k-chunks
#define NCC 8                  // c-chunks
#define NSTAGES (NKC * NCC)    // 64

#define ZS_F   (CC * TM)       // 1024 floats (4KB)
#define WS_F   (CC * TN)       // 4096 floats (16KB)
#define STAGE_F (ZS_F + WS_F)  // 5120 floats (20KB)
#define SMEM_BYTES (2 * STAGE_F * 4)   // 40960

// Normalized codebook: row-major (gather) and stage-packed (GEMM loads)
__device__ float g_wn[K_CODES * C_DIM];   // [k][c]
__device__ float g_wp[C_DIM * K_CODES];   // [stage s][c&31][k&127]

// ---------------------------------------------------------------------------
__device__ __forceinline__ unsigned long long dupf(float x) {
    unsigned long long r;
    asm("mov.b64 %0, {%1, %1};" : "=l"(r) : "f"(x));
    return r;
}
__device__ __forceinline__ void ffma2(unsigned long long& d,
                                      unsigned long long a,
                                      unsigned long long b) {
    asm("fma.rn.f32x2 %0, %1, %2, %0;" : "+l"(d) : "l"(a), "l"(b));
}
__device__ __forceinline__ void unpack2(unsigned long long v, float& lo, float& hi) {
    asm("mov.b64 {%0, %1}, %2;" : "=f"(lo), "=f"(hi) : "l"(v));
}
__device__ __forceinline__ unsigned int smem_u32(const void* p) {
    return (unsigned int)__cvta_generic_to_shared(p);
}
__device__ __forceinline__ void cp16(unsigned int dst, const void* src) {
    asm volatile("cp.async.cg.shared.global [%0], [%1], 16;" :: "r"(dst), "l"(src));
}
__device__ __forceinline__ void cp_commit() {
    asm volatile("cp.async.commit_group;");
}
template<int N>
__device__ __forceinline__ void cp_wait() {
    asm volatile("cp.async.wait_group %0;" :: "n"(N));
}

// ---------------------------------------------------------------------------
// Kernel 1: L2-normalize codebook rows -> g_wn row-major + g_wp stage-packed.
// stage s = (k>>7)*8 + (c>>5); within stage: [c&31][k&127]
// ---------------------------------------------------------------------------
__global__ void vq_norm_weight_kernel(const float* __restrict__ w) {
    const int k = blockIdx.x;
    const int t = threadIdx.x;           // channel
    float v = w[k * C_DIM + t];
    float s = v * v;
    #pragma unroll
    for (int off = 16; off; off >>= 1)
        s += __shfl_xor_sync(0xffffffffu, s, off);
    __shared__ float ssum[8];
    if ((t & 31) == 0) ssum[t >> 5] = s;
    __syncthreads();
    float tot = ssum[0] + ssum[1] + ssum[2] + ssum[3]
              + ssum[4] + ssum[5] + ssum[6] + ssum[7];
    float den = fmaxf(sqrtf(tot), 1e-12f);
    float o = v / den;                   // full-precision fp32 divide (match jnp)
    g_wn[k * C_DIM + t] = o;
    int stage = ((k >> 7) << 3) + (t >> 5);
    g_wp[(stage << 12) + ((t & 31) << 7) + (k & 127)] = o;
}

// ---------------------------------------------------------------------------
// Kernel 2: argmax_k <z_n, w_k> + gather z_q.
// 1024 blocks x 128 threads; 40KB dynamic smem (2-stage ring) -> 5 blocks/SM.
// ---------------------------------------------------------------------------
__global__ __launch_bounds__(NTHREADS, 5)
void vq_argmax_kernel(const float* __restrict__ z,
                      float* __restrict__ out,
                      int write_idx) {
    extern __shared__ float sm[];        // 2 * STAGE_F

    const int tid = threadIdx.x;
    const int tx = tid & 15;             // code lane
    const int ty = tid >> 4;             // pixel row -> pixels ty*4..ty*4+3
    const int n0 = blockIdx.x * TM;
    const int b   = n0 >> 10;
    const int hw0 = n0 & 1023;
    const float* zbase = z + (((size_t)b * C_DIM) << 10) + hw0;

    // ---- stage fill: all linear 16B cp.async ----
    auto fill = [&](int s) {
        float* buf = sm + (s & 1) * STAGE_F;
        const int ccI = s & (NCC - 1);
        #pragma unroll
        for (int t = 0; t < 2; t++) {            // zs: 256 float4
            int i  = tid + t * NTHREADS;
            int c  = i >> 3;
            int p4 = i & 7;
            cp16(smem_u32(buf + i * 4),
                 zbase + (((size_t)(ccI * CC + c)) << 10) + p4 * 4);
        }
        const float* wsrc = g_wp + ((size_t)s << 12);
        #pragma unroll
        for (int t = 0; t < 8; t++) {            // ws: 1024 float4
            int i = tid + t * NTHREADS;
            cp16(smem_u32(buf + ZS_F + i * 4), wsrc + i * 4);
        }
        cp_commit();
    };

    fill(0);

    float rbv[4];
    int   rbi[4];
    #pragma unroll
    for (int i = 0; i < 4; i++) { rbv[i] = -CUDART_INF_F; rbi[i] = 0; }

    int s = 0;
    for (int kcI = 0; kcI < NKC; kcI++) {
        unsigned long long acc[4][4];    // [pixel][code-pair]
        #pragma unroll
        for (int i = 0; i < 4; i++)
            #pragma unroll
            for (int j = 0; j < 4; j++) acc[i][j] = 0ull;

        for (int ccI = 0; ccI < NCC; ccI++, s++) {
            cp_wait<0>();                 // fill(s) complete
            __syncthreads();              // everyone done computing s-1
            if (s + 1 < NSTAGES) fill(s + 1);   // overwrites buffer of s-1

            const float* zb = sm + (s & 1) * STAGE_F;
            const float* wb = zb + ZS_F;

            #pragma unroll 4
            for (int c = 0; c < CC; c++) {
                float4 zv = *(const float4*)(zb + c * TM + (ty << 2));
                const float* wr = wb + c * TN + (tx << 2);
                ulonglong2 w0 = *(const ulonglong2*)wr;         // codes tx*4..+3
                ulonglong2 w1 = *(const ulonglong2*)(wr + 64);  // codes 64+tx*4..+3
                unsigned long long zp0 = dupf(zv.x);
                unsigned long long zp1 = dupf(zv.y);
                unsigned long long zp2 = dupf(zv.z);
                unsigned long long zp3 = dupf(zv.w);
                ffma2(acc[0][0], zp0, w0.x); ffma2(acc[0][1], zp0, w0.y);
                ffma2(acc[0][2], zp0, w1.x); ffma2(acc[0][3], zp0, w1.y);
                ffma2(acc[1][0], zp1, w0.x); ffma2(acc[1][1], zp1, w0.y);
                ffma2(acc[1][2], zp1, w1.x); ffma2(acc[1][3], zp1, w1.y);
                ffma2(acc[2][0], zp2, w0.x); ffma2(acc[2][1], zp2, w0.y);
                ffma2(acc[2][2], zp2, w1.x); ffma2(acc[2][3], zp2, w1.y);
                ffma2(acc[3][0], zp3, w0.x); ffma2(acc[3][1], zp3, w0.y);
                ffma2(acc[3][2], zp3, w1.x); ffma2(acc[3][3], zp3, w1.y);
            }
        }

        // ---- chunk argmax. j-th pair codes: see k0 below (increasing k scan) ----
        const int kc = kcI * TN;
        #pragma unroll
        for (int i = 0; i < 4; i++) {
            float bv = -CUDART_INF_F;
            int   bk = 0;
            #pragma unroll
            for (int j = 0; j < 4; j++) {
                float lo, hi;
                unpack2(acc[i][j], lo, hi);
                int k0 = kc + (tx << 2) + ((j >> 1) << 6) + ((j & 1) << 1);
                if (lo > bv) { bv = lo; bk = k0; }       // strict >: first max wins
                if (hi > bv) { bv = hi; bk = k0 + 1; }
            }
            #pragma unroll
            for (int off = 8; off; off >>= 1) {          // across 16 tx lanes
                float ov = __shfl_xor_sync(0xffffffffu, bv, off);
                int   ok = __shfl_xor_sync(0xffffffffu, bk, off);
                if (ov > bv || (ov == bv && ok < bk)) { bv = ov; bk = ok; }
            }
            if (bv > rbv[i]) { rbv[i] = bv; rbi[i] = bk; }   // later kc strictly >
        }
    }

    // ---- publish per-pixel indices ----
    __syncthreads();                 // all compute done; smem reusable
    int* sbidx = (int*)sm;
    if (tx == 0) {
        #pragma unroll
        for (int i = 0; i < 4; i++) sbidx[(ty << 2) + i] = rbi[i];
    }
    __syncthreads();

    // ---- write z_q: out[b][c][hw0+p] = g_wn[idx[p]][c], coalesced over p ----
    #pragma unroll 4
    for (int i = tid; i < C_DIM * TM; i += NTHREADS) {
        int p = i & (TM - 1);
        int c = i >> 5;
        out[(((size_t)(b * C_DIM + c)) << 10) + hw0 + p] =
            g_wn[(size_t)sbidx[p] * C_DIM + c];
    }
    if (write_idx && tid < TM) {
        out[ZQ_ELEMS + n0 + tid] = (float)sbidx[tid];
    }
}

// ---------------------------------------------------------------------------
extern "C" void kernel_launch(void* const* d_in, const int* in_sizes, int n_in,
                              void* d_out, int out_size) {
    const float* z_e    = (const float*)d_in[0];
    const float* weight = (const float*)d_in[1];
    float* out = (float*)d_out;

    const int write_idx = (out_size >= ZQ_ELEMS + N_PIX) ? 1 : 0;

    static int init_done = 0;
    if (!init_done) {
        cudaFuncSetAttribute(vq_argmax_kernel,
                             cudaFuncAttributeMaxDynamicSharedMemorySize,
                             SMEM_BYTES);
        cudaFuncSetAttribute(vq_argmax_kernel,
                             cudaFuncAttributePreferredSharedMemoryCarveout,
                             cudaSharedmemCarveoutMaxShared);
        init_done = 1;
    }

    vq_norm_weight_kernel<<<K_CODES, C_DIM>>>(weight);
    vq_argmax_kernel<<<N_PIX / TM, NTHREADS, SMEM_BYTES>>>(z_e, out, write_idx);
}